// round 8
// baseline (speedup 1.0000x reference)
#include <cuda_runtime.h>
#include <cuda_bf16.h>
#include <cstdint>

// ---------------------------------------------------------------------------
// Problem constants (B=2, S=2048, H=1024, NH=16, NKV=8, D=128)
// ---------------------------------------------------------------------------
constexpr int B_   = 2;
constexpr int S_   = 2048;
constexpr int H_   = 1024;
constexpr int NH_  = 16;
constexpr int NKV_ = 8;
constexpr int D_   = 128;
constexpr int TOK  = B_ * S_;            // 4096 tokens

// Scratch (device globals; no allocation allowed)
__device__ float g_q [TOK * NH_  * D_];
__device__ float g_k [TOK * NKV_ * D_];
__device__ float g_v [TOK * NKV_ * D_];
__device__ float g_ao[TOK * NH_  * D_];
// bf16 hi/lo split attention operands
__device__ __nv_bfloat16 g_qh[TOK * NH_  * D_], g_ql[TOK * NH_  * D_];
__device__ __nv_bfloat16 g_kh[TOK * NKV_ * D_], g_kl[TOK * NKV_ * D_];
__device__ __nv_bfloat16 g_vh[TOK * NKV_ * D_], g_vl[TOK * NKV_ * D_];

#define DEV_INLINE __device__ __forceinline__

// ---------------------------------------------------------------------------
// helpers
// ---------------------------------------------------------------------------
DEV_INLINE uint32_t cvt_bf16x2(float hi_elem, float lo_elem) {
    uint32_t r;
    asm("cvt.rn.bf16x2.f32 %0, %1, %2;" : "=r"(r) : "f"(hi_elem), "f"(lo_elem));
    return r;
}
// split two fp32 (f0 -> low lane, f1 -> high lane) into bf16 hi-pair + lo-pair
DEV_INLINE void split_pair(float f0, float f1, uint32_t& hiw, uint32_t& low) {
    hiw = cvt_bf16x2(f1, f0);
    float h0 = __uint_as_float(hiw << 16);
    float h1 = __uint_as_float(hiw & 0xFFFF0000u);
    low = cvt_bf16x2(f1 - h1, f0 - h0);
}
DEV_INLINE void ldsm_x4(uint32_t* r, uint32_t addr) {
    asm volatile("ldmatrix.sync.aligned.m8n8.x4.shared.b16 {%0,%1,%2,%3}, [%4];"
                 : "=r"(r[0]), "=r"(r[1]), "=r"(r[2]), "=r"(r[3]) : "r"(addr));
}
DEV_INLINE void ldsm_x4_trans(uint32_t* r, uint32_t addr) {
    asm volatile("ldmatrix.sync.aligned.m8n8.x4.trans.shared.b16 {%0,%1,%2,%3}, [%4];"
                 : "=r"(r[0]), "=r"(r[1]), "=r"(r[2]), "=r"(r[3]) : "r"(addr));
}
DEV_INLINE void mma_bf16(float* c, const uint32_t* a, const uint32_t* b) {
    asm volatile(
        "mma.sync.aligned.m16n8k16.row.col.f32.bf16.bf16.f32 "
        "{%0,%1,%2,%3}, {%4,%5,%6,%7}, {%8,%9}, {%0,%1,%2,%3};"
        : "+f"(c[0]), "+f"(c[1]), "+f"(c[2]), "+f"(c[3])
        : "r"(a[0]), "r"(a[1]), "r"(a[2]), "r"(a[3]), "r"(b[0]), "r"(b[1]));
}
DEV_INLINE uint32_t smem_u32(const void* p) {
    uint32_t a;
    asm("{ .reg .u64 t; cvta.to.shared.u64 t, %1; cvt.u32.u64 %0, t; }"
        : "=r"(a) : "l"(p));
    return a;
}
DEV_INLINE void cp16(uint32_t dst, const void* src) {
    asm volatile("cp.async.cg.shared.global [%0], [%1], 16;"
                 :: "r"(dst), "l"(src) : "memory");
}
DEV_INLINE void cp_commit() { asm volatile("cp.async.commit_group;" ::: "memory"); }
DEV_INLINE void cp_wait1()  { asm volatile("cp.async.wait_group 1;" ::: "memory"); }
DEV_INLINE void cp_wait0()  { asm volatile("cp.async.wait_group 0;" ::: "memory"); }
// named barriers (producer/consumer handshake), count = 384
DEV_INLINE void bar_sync(int id)   { asm volatile("bar.sync %0, 384;"   :: "r"(id) : "memory"); }
DEV_INLINE void bar_arrive(int id) { asm volatile("bar.arrive %0, 384;" :: "r"(id) : "memory"); }

// ---------------------------------------------------------------------------
// Warp-specialized bf16x3 tensor-core NT GEMM.
// C[m,n] = sum_k A[m,k]*B[n,k].  CTA tile 128x128, BK=32, 384 threads:
//   warps 0-3  : producers (LDG fp32, bf16 hi/lo split, STS)
//   warps 4-11 : consumers (ldsm + mma; 4m x 2n, warp tile 32x64)
// Double-buffered smem {Ahi,Alo,Bhi,Blo} x2, named-barrier handshake.
// 3 products: Ah*Bh + Ah*Bl + Al*Bh.
// ---------------------------------------------------------------------------
constexpr int GMATB = 10240;           // 128 * 80 bytes per split tile
constexpr int GBUFB = 4 * GMATB;       // 40960 per double-buffer slot
constexpr int GSMEM = 2 * GBUFB;       // 81920

DEV_INLINE void gemm_body(const float* __restrict__ A, const float* __restrict__ Bm,
                          float* __restrict__ C, int K, int N, int m0, int n0,
                          char* smem, uint32_t sb)
{
    const int tid  = threadIdx.x;
    const int lane = tid & 31;
    const int NC   = K / 32;

    if (tid < 128) {
        // ===================== producer =====================
        const int t = tid;                      // row 0..127 of both A and B
        const float* Arow = A  + (size_t)(m0 + t) * K;
        const float* Brow = Bm + (size_t)(n0 + t) * K;

        float4 ra[8], rb[8];
#pragma unroll
        for (int i = 0; i < 8; i++) {
            ra[i] = *reinterpret_cast<const float4*>(Arow + i * 4);
            rb[i] = *reinterpret_cast<const float4*>(Brow + i * 4);
        }

        for (int c = 0; c < NC; c++) {
            const int b = c & 1;
            char* bp = smem + b * GBUFB;
            if (c >= 2) bar_sync(3 + b);        // wait EMPTY(b)

            const uint32_t off = (uint32_t)t * 80;
            uint32_t h[16], l[16];
#pragma unroll
            for (int i = 0; i < 8; i++) {
                split_pair(ra[i].x, ra[i].y, h[2 * i],     l[2 * i]);
                split_pair(ra[i].z, ra[i].w, h[2 * i + 1], l[2 * i + 1]);
            }
#pragma unroll
            for (int j = 0; j < 4; j++) {
                *reinterpret_cast<uint4*>(bp + off + j * 16) =
                    make_uint4(h[4 * j], h[4 * j + 1], h[4 * j + 2], h[4 * j + 3]);
                *reinterpret_cast<uint4*>(bp + GMATB + off + j * 16) =
                    make_uint4(l[4 * j], l[4 * j + 1], l[4 * j + 2], l[4 * j + 3]);
            }
#pragma unroll
            for (int i = 0; i < 8; i++) {
                split_pair(rb[i].x, rb[i].y, h[2 * i],     l[2 * i]);
                split_pair(rb[i].z, rb[i].w, h[2 * i + 1], l[2 * i + 1]);
            }
#pragma unroll
            for (int j = 0; j < 4; j++) {
                *reinterpret_cast<uint4*>(bp + 2 * GMATB + off + j * 16) =
                    make_uint4(h[4 * j], h[4 * j + 1], h[4 * j + 2], h[4 * j + 3]);
                *reinterpret_cast<uint4*>(bp + 3 * GMATB + off + j * 16) =
                    make_uint4(l[4 * j], l[4 * j + 1], l[4 * j + 2], l[4 * j + 3]);
            }
            bar_arrive(1 + b);                  // signal FULL(b)

            if (c + 1 < NC) {                   // prefetch next chunk
                const int k0 = (c + 1) * 32;
#pragma unroll
                for (int i = 0; i < 8; i++) {
                    ra[i] = *reinterpret_cast<const float4*>(Arow + k0 + i * 4);
                    rb[i] = *reinterpret_cast<const float4*>(Brow + k0 + i * 4);
                }
            }
        }
        return;                                 // producers exit
    }

    // ===================== consumer =====================
    const int cw = (tid >> 5) - 4;              // 0..7
    const int wm = cw & 3;                      // 4 m-warps
    const int wn = cw >> 2;                     // 2 n-warps

    float Cacc[2][8][4];
#pragma unroll
    for (int mi = 0; mi < 2; mi++)
#pragma unroll
        for (int nf = 0; nf < 8; nf++)
#pragma unroll
            for (int e = 0; e < 4; e++) Cacc[mi][nf][e] = 0.f;

    const uint32_t lrow = (uint32_t)(lane & 15);
    const uint32_t lcol = (uint32_t)(lane >> 4) * 16;

    for (int c = 0; c < NC; c++) {
        const int b = c & 1;
        const uint32_t bufs = sb + b * GBUFB;
        bar_sync(1 + b);                        // wait FULL(b)

#pragma unroll
        for (int ks = 0; ks < 2; ks++) {
            uint32_t afrag[2][2][4];
            uint32_t bfr[2][8][2];
#pragma unroll
            for (int sel = 0; sel < 2; sel++) {
#pragma unroll
                for (int mi = 0; mi < 2; mi++) {
                    const uint32_t addr = bufs + (uint32_t)sel * GMATB +
                        ((uint32_t)(wm * 32 + mi * 16) + lrow) * 80 +
                        (uint32_t)ks * 32 + lcol;
                    ldsm_x4(afrag[sel][mi], addr);
                }
#pragma unroll
                for (int ng = 0; ng < 4; ng++) {
                    uint32_t t4[4];
                    const uint32_t addr = bufs + 2 * GMATB + (uint32_t)sel * GMATB +
                        ((uint32_t)(wn * 64 + ng * 16) + lrow) * 80 +
                        (uint32_t)ks * 32 + lcol;
                    ldsm_x4(t4, addr);
                    bfr[sel][ng * 2][0]     = t4[0];
                    bfr[sel][ng * 2][1]     = t4[2];
                    bfr[sel][ng * 2 + 1][0] = t4[1];
                    bfr[sel][ng * 2 + 1][1] = t4[3];
                }
            }
#pragma unroll
            for (int mi = 0; mi < 2; mi++)
#pragma unroll
                for (int nf = 0; nf < 8; nf++)
                    mma_bf16(Cacc[mi][nf], afrag[0][mi], bfr[0][nf]);
#pragma unroll
            for (int mi = 0; mi < 2; mi++)
#pragma unroll
                for (int nf = 0; nf < 8; nf++)
                    mma_bf16(Cacc[mi][nf], afrag[0][mi], bfr[1][nf]);
#pragma unroll
            for (int mi = 0; mi < 2; mi++)
#pragma unroll
                for (int nf = 0; nf < 8; nf++)
                    mma_bf16(Cacc[mi][nf], afrag[1][mi], bfr[0][nf]);
        }

        if (c + 2 < NC) bar_arrive(3 + b);      // signal EMPTY(b)
    }

    // epilogue (consumers only)
#pragma unroll
    for (int mi = 0; mi < 2; mi++) {
        const int row = m0 + wm * 32 + mi * 16 + (lane >> 2);
#pragma unroll
        for (int nf = 0; nf < 8; nf++) {
            const int col = n0 + wn * 64 + nf * 8 + (lane & 3) * 2;
            *reinterpret_cast<float2*>(C + (size_t)row * N + col) =
                make_float2(Cacc[mi][nf][0], Cacc[mi][nf][1]);
            *reinterpret_cast<float2*>(C + (size_t)(row + 8) * N + col) =
                make_float2(Cacc[mi][nf][2], Cacc[mi][nf][3]);
        }
    }
}

// Merged QKV projection: grid (32 n-tiles routed, 32 m-tiles)
__global__ void __launch_bounds__(384, 1)
gemm_qkv(const float* __restrict__ A,
         const float* __restrict__ Wq, const float* __restrict__ Wk,
         const float* __restrict__ Wv,
         float* __restrict__ q, float* __restrict__ k, float* __restrict__ v)
{
    extern __shared__ char smem[];
    const uint32_t sb = smem_u32(smem);
    const int bx = blockIdx.x;
    const int m0 = blockIdx.y * 128;

    const float* Bm; float* C; int N; int n0;
    if (bx < 16)      { Bm = Wq; C = q; N = NH_ * D_;  n0 = bx * 128; }
    else if (bx < 24) { Bm = Wk; C = k; N = NKV_ * D_; n0 = (bx - 16) * 128; }
    else              { Bm = Wv; C = v; N = NKV_ * D_; n0 = (bx - 24) * 128; }

    gemm_body(A, Bm, C, H_, N, m0, n0, smem, sb);
}

// Generic GEMM (output projection)
__global__ void __launch_bounds__(384, 1)
gemm_nt(const float* __restrict__ A, const float* __restrict__ Bm,
        float* __restrict__ C, int M, int N, int K)
{
    extern __shared__ char smem[];
    const uint32_t sb = smem_u32(smem);
    gemm_body(A, Bm, C, K, N, blockIdx.y * 128, blockIdx.x * 128, smem, sb);
}

// ---------------------------------------------------------------------------
// Fused RMSNorm + RoPE + bf16 hi/lo split. Warp-per-row (D=128, 4 els/lane).
// rows = TOK * 32 (hh: 0-15 q, 16-23 k, 24-31 v). 256-thread blocks, 8 rows.
// ---------------------------------------------------------------------------
__global__ void __launch_bounds__(256)
rms_rope_split2(const float* __restrict__ qbuf, const float* __restrict__ kbuf,
                const float* __restrict__ vbuf,
                const float* __restrict__ cosb, const float* __restrict__ sinb,
                const float* __restrict__ qw,   const float* __restrict__ kw,
                __nv_bfloat16* __restrict__ qh, __nv_bfloat16* __restrict__ ql,
                __nv_bfloat16* __restrict__ kh, __nv_bfloat16* __restrict__ kl,
                __nv_bfloat16* __restrict__ vh, __nv_bfloat16* __restrict__ vl)
{
    const int rrow = blockIdx.x * 8 + (threadIdx.x >> 5);
    const int l    = threadIdx.x & 31;
    const int t    = rrow >> 5;
    const int hh   = rrow & 31;

    if (hh >= 24) {                      // v: split only
        const size_t base = (size_t)t * (NKV_ * D_) + (hh - 24) * D_ + l * 4;
        const float4 x = *reinterpret_cast<const float4*>(vbuf + base);
        uint32_t h0, l0, h1, l1;
        split_pair(x.x, x.y, h0, l0);
        split_pair(x.z, x.w, h1, l1);
        *reinterpret_cast<uint2*>(vh + base) = make_uint2(h0, h1);
        *reinterpret_cast<uint2*>(vl + base) = make_uint2(l0, l1);
        return;
    }

    const float* src; const float* w;
    __nv_bfloat16 *oh, *ol;
    size_t base;
    if (hh < 16) {
        base = (size_t)t * (NH_ * D_) + hh * D_ + l * 4;
        src = qbuf; w = qw; oh = qh; ol = ql;
    } else {
        base = (size_t)t * (NKV_ * D_) + (hh - 16) * D_ + l * 4;
        src = kbuf; w = kw; oh = kh; ol = kl;
    }

    const float4 x = *reinterpret_cast<const float4*>(src + base);
    float ss = x.x * x.x + x.y * x.y + x.z * x.z + x.w * x.w;
#pragma unroll
    for (int off = 16; off >= 1; off >>= 1) ss += __shfl_xor_sync(0xffffffffu, ss, off);
    const float inv = rsqrtf(ss * (1.0f / 128.0f) + 1e-6f);

    const float4 wv = *reinterpret_cast<const float4*>(w + l * 4);
    const float4 cv = *reinterpret_cast<const float4*>(cosb + (size_t)t * D_ + l * 4);
    const float4 sv = *reinterpret_cast<const float4*>(sinb + (size_t)t * D_ + l * 4);

    const float z0 = x.x * wv.x, z1 = x.y * wv.y, z2 = x.z * wv.z, z3 = x.w * wv.w;
    const float p0 = __shfl_xor_sync(0xffffffffu, z0, 16);
    const float p1 = __shfl_xor_sync(0xffffffffu, z1, 16);
    const float p2 = __shfl_xor_sync(0xffffffffu, z2, 16);
    const float p3 = __shfl_xor_sync(0xffffffffu, z3, 16);
    const float sgn = (l < 16) ? -1.f : 1.f;

    const float y0 = (z0 * cv.x + sgn * p0 * sv.x) * inv;
    const float y1 = (z1 * cv.y + sgn * p1 * sv.y) * inv;
    const float y2 = (z2 * cv.z + sgn * p2 * sv.z) * inv;
    const float y3 = (z3 * cv.w + sgn * p3 * sv.w) * inv;

    uint32_t h0, l0w, h1, l1w;
    split_pair(y0, y1, h0, l0w);
    split_pair(y2, y3, h1, l1w);
    *reinterpret_cast<uint2*>(oh + base) = make_uint2(h0, h1);
    *reinterpret_cast<uint2*>(ol + base) = make_uint2(l0w, l1w);
}

// ---------------------------------------------------------------------------
// Tensor-core flash attention (bf16x3, causal, GQA n_rep=2). Round-4 proven.
// BQ=128, BKV=64, D=128. 256 threads = 8 warps, warp w -> q rows w*16..+15.
// ---------------------------------------------------------------------------
constexpr int AQ_BYTES  = 128 * 272;                 // 34816
constexpr int AKV_BYTES = 64 * 272;                  // 17408
constexpr int ABUF0     = 2 * AQ_BYTES;              // 69632
constexpr int ABUFSZ    = 4 * AKV_BYTES;             // 69632
constexpr int ATTN_SMEM = ABUF0 + 2 * ABUFSZ;        // 208896

__global__ void __launch_bounds__(256, 1)
attn_bf16_kernel(const __nv_bfloat16* __restrict__ qh, const __nv_bfloat16* __restrict__ ql,
                 const __nv_bfloat16* __restrict__ kh, const __nv_bfloat16* __restrict__ kl,
                 const __nv_bfloat16* __restrict__ vh, const __nv_bfloat16* __restrict__ vl,
                 float* __restrict__ ao)
{
    extern __shared__ char smem[];
    const uint32_t sb = smem_u32(smem);

    const int tid  = threadIdx.x;
    const int lane = tid & 31;
    const int w    = tid >> 5;
    const int qi   = gridDim.x - 1 - blockIdx.x;
    const int h    = blockIdx.y;
    const int b    = blockIdx.z;
    const int kvh  = h >> 1;

#pragma unroll
    for (int i = 0; i < 8; i++) {
        const int idx = tid + i * 256;
        const int row = idx >> 4, ch = idx & 15;
        const size_t g = ((size_t)(b * S_) + qi * 128 + row) * (NH_ * D_) + h * D_ + ch * 8;
        cp16(sb + row * 272 + ch * 16,            qh + g);
        cp16(sb + AQ_BYTES + row * 272 + ch * 16, ql + g);
    }
    {
        const uint32_t buf = sb + ABUF0;
#pragma unroll
        for (int i = 0; i < 4; i++) {
            const int idx = tid + i * 256;
            const int row = idx >> 4, ch = idx & 15;
            const size_t g = ((size_t)(b * S_) + row) * (NKV_ * D_) + kvh * D_ + ch * 8;
            const uint32_t so = buf + row * 272 + ch * 16;
            cp16(so,                 kh + g);
            cp16(so + AKV_BYTES,     kl + g);
            cp16(so + 2 * AKV_BYTES, vh + g);
            cp16(so + 3 * AKV_BYTES, vl + g);
        }
    }
    cp_commit();

    float oacc[16][4];
#pragma unroll
    for (int i = 0; i < 16; i++)
#pragma unroll
        for (int e = 0; e < 4; e++) oacc[i][e] = 0.f;
    float m_i[2] = {-1e30f, -1e30f};
    float l_i[2] = {0.f, 0.f};

    const uint32_t lrow16 = (uint32_t)(lane & 15);
    const uint32_t lhalf  = (uint32_t)(lane >> 4) * 16;
    const int jmax = 2 * qi + 1;

    for (int jb = 0; jb <= jmax; jb++) {
        if (jb < jmax) {
            const uint32_t buf = sb + ABUF0 + ((jb + 1) & 1) * ABUFSZ;
#pragma unroll
            for (int i = 0; i < 4; i++) {
                const int idx = tid + i * 256;
                const int row = idx >> 4, ch = idx & 15;
                const size_t g = ((size_t)(b * S_) + (jb + 1) * 64 + row) * (NKV_ * D_) +
                                 kvh * D_ + ch * 8;
                const uint32_t so = buf + row * 272 + ch * 16;
                cp16(so,                 kh + g);
                cp16(so + AKV_BYTES,     kl + g);
                cp16(so + 2 * AKV_BYTES, vh + g);
                cp16(so + 3 * AKV_BYTES, vl + g);
            }
            cp_commit();
            cp_wait1();
        } else {
            cp_wait0();
        }
        __syncthreads();

        const uint32_t kb = sb + ABUF0 + (jb & 1) * ABUFSZ;
        const bool skip = (jb * 64) > (qi * 128 + w * 16 + 15);

        if (!skip) {
            float sacc[8][4];
#pragma unroll
            for (int i = 0; i < 8; i++)
#pragma unroll
                for (int e = 0; e < 4; e++) sacc[i][e] = 0.f;

            const uint32_t qbase = sb + ((uint32_t)(w * 16) + lrow16) * 272 + lhalf;
#pragma unroll
            for (int ks = 0; ks < 8; ks++) {
                uint32_t ahi[4], alo[4];
                ldsm_x4(ahi, qbase + ks * 32);
                ldsm_x4(alo, qbase + AQ_BYTES + ks * 32);
#pragma unroll
                for (int ng = 0; ng < 4; ng++) {
                    uint32_t t[4], u[4];
                    const uint32_t ka = kb + ((uint32_t)(ng * 16) + lrow16) * 272 + ks * 32 + lhalf;
                    ldsm_x4(t, ka);
                    ldsm_x4(u, ka + AKV_BYTES);
                    uint32_t bh0[2] = {t[0], t[2]}, bh1[2] = {t[1], t[3]};
                    uint32_t bl0[2] = {u[0], u[2]}, bl1[2] = {u[1], u[3]};
                    mma_bf16(sacc[ng * 2],     ahi, bh0);
                    mma_bf16(sacc[ng * 2 + 1], ahi, bh1);
                    mma_bf16(sacc[ng * 2],     ahi, bl0);
                    mma_bf16(sacc[ng * 2 + 1], ahi, bl1);
                    mma_bf16(sacc[ng * 2],     alo, bh0);
                    mma_bf16(sacc[ng * 2 + 1], alo, bh1);
                }
            }

            const float sc = 0.088388347648318447f;
            const bool domask = (jb * 64 + 63) > (qi * 128 + w * 16);
#pragma unroll
            for (int nf = 0; nf < 8; nf++)
#pragma unroll
                for (int e = 0; e < 4; e++) {
                    float s = sacc[nf][e] * sc;
                    if (domask) {
                        const int col = jb * 64 + nf * 8 + ((lane & 3) << 1) + (e & 1);
                        const int row = qi * 128 + w * 16 + (lane >> 2) + ((e >> 1) << 3);
                        if (col > row) s = -1e30f;
                    }
                    sacc[nf][e] = s;
                }

#pragma unroll
            for (int r2 = 0; r2 < 2; r2++) {
                float mx = -1e30f;
#pragma unroll
                for (int nf = 0; nf < 8; nf++)
                    mx = fmaxf(mx, fmaxf(sacc[nf][2 * r2], sacc[nf][2 * r2 + 1]));
                mx = fmaxf(mx, __shfl_xor_sync(0xffffffffu, mx, 1));
                mx = fmaxf(mx, __shfl_xor_sync(0xffffffffu, mx, 2));
                const float mn = fmaxf(m_i[r2], mx);
                const float alpha = __expf(m_i[r2] - mn);
                m_i[r2] = mn;
                float rs = 0.f;
#pragma unroll
                for (int nf = 0; nf < 8; nf++) {
                    float p0 = __expf(sacc[nf][2 * r2]     - mn);
                    float p1 = __expf(sacc[nf][2 * r2 + 1] - mn);
                    sacc[nf][2 * r2]     = p0;
                    sacc[nf][2 * r2 + 1] = p1;
                    rs += p0 + p1;
                }
                rs += __shfl_xor_sync(0xffffffffu, rs, 1);
                rs += __shfl_xor_sync(0xffffffffu, rs, 2);
                l_i[r2] = l_i[r2] * alpha + rs;
#pragma unroll
                for (int ndf = 0; ndf < 16; ndf++) {
                    oacc[ndf][2 * r2]     *= alpha;
                    oacc[ndf][2 * r2 + 1] *= alpha;
                }
            }

#pragma unroll
            for (int kk = 0; kk < 4; kk++) {
                uint32_t phi[4], plo[4];
                split_pair(sacc[2 * kk][0],     sacc[2 * kk][1],     phi[0], plo[0]);
                split_pair(sacc[2 * kk][2],     sacc[2 * kk][3],     phi[1], plo[1]);
                split_pair(sacc[2 * kk + 1][0], sacc[2 * kk + 1][1], phi[2], plo[2]);
                split_pair(sacc[2 * kk + 1][2], sacc[2 * kk + 1][3], phi[3], plo[3]);
#pragma unroll
                for (int ndg = 0; ndg < 8; ndg++) {
                    uint32_t t[4], u[4];
                    const uint32_t va = kb + 2 * AKV_BYTES +
                        ((uint32_t)(kk * 16) + lrow16) * 272 + ndg * 32 + lhalf;
                    ldsm_x4_trans(t, va);
                    ldsm_x4_trans(u, va + AKV_BYTES);
                    uint32_t bh0[2] = {t[0], t[1]}, bh1[2] = {t[2], t[3]};
                    uint32_t bl0[2] = {u[0], u[1]}, bl1[2] = {u[2], u[3]};
                    mma_bf16(oacc[ndg * 2],     phi, bh0);
                    mma_bf16(oacc[ndg * 2 + 1], phi, bh1);
                    mma_bf16(oacc[ndg * 2],     phi, bl0);
                    mma_bf16(oacc[ndg * 2 + 1], phi, bl1);
                    mma_bf16(oacc[ndg * 2],     plo, bh0);
                    mma_bf16(oacc[ndg * 2 + 1], plo, bh1);
                }
            }
        }
        __syncthreads();
    }

    const float i0 = 1.0f / l_i[0];
    const float i1 = 1.0f / l_i[1];
    const int row0 = qi * 128 + w * 16 + (lane >> 2);
    const size_t base0 = ((size_t)(b * S_) + row0) * (NH_ * D_) + h * D_ + (lane & 3) * 2;
    const size_t base1 = base0 + (size_t)8 * (NH_ * D_);
#pragma unroll
    for (int ndf = 0; ndf < 16; ndf++) {
        *reinterpret_cast<float2*>(ao + base0 + ndf * 8) =
            make_float2(oacc[ndf][0] * i0, oacc[ndf][1] * i0);
        *reinterpret_cast<float2*>(ao + base1 + ndf * 8) =
            make_float2(oacc[ndf][2] * i1, oacc[ndf][3] * i1);
    }
}

// ---------------------------------------------------------------------------
// Launch
// ---------------------------------------------------------------------------
extern "C" void kernel_launch(void* const* d_in, const int* in_sizes, int n_in,
                              void* d_out, int out_size)
{
    const float* hidden = (const float*)d_in[0];
    const float* cosb   = (const float*)d_in[1];
    const float* sinb   = (const float*)d_in[2];
    const float* Wq     = (const float*)d_in[3];
    const float* Wk     = (const float*)d_in[4];
    const float* Wv     = (const float*)d_in[5];
    const float* Wo     = (const float*)d_in[6];
    const float* qw     = (const float*)d_in[7];
    const float* kw     = (const float*)d_in[8];
    float* out = (float*)d_out;

    float *gq, *gk, *gv, *gao;
    cudaGetSymbolAddress((void**)&gq,  g_q);
    cudaGetSymbolAddress((void**)&gk,  g_k);
    cudaGetSymbolAddress((void**)&gv,  g_v);
    cudaGetSymbolAddress((void**)&gao, g_ao);
    __nv_bfloat16 *qh, *ql, *kh, *kl, *vh, *vl;
    cudaGetSymbolAddress((void**)&qh, g_qh);
    cudaGetSymbolAddress((void**)&ql, g_ql);
    cudaGetSymbolAddress((void**)&kh, g_kh);
    cudaGetSymbolAddress((void**)&kl, g_kl);
    cudaGetSymbolAddress((void**)&vh, g_vh);
    cudaGetSymbolAddress((void**)&vl, g_vl);

    cudaFuncSetAttribute((const void*)gemm_qkv,
                         cudaFuncAttributeMaxDynamicSharedMemorySize, GSMEM);
    cudaFuncSetAttribute((const void*)gemm_nt,
                         cudaFuncAttributeMaxDynamicSharedMemorySize, GSMEM);
    cudaFuncSetAttribute((const void*)attn_bf16_kernel,
                         cudaFuncAttributeMaxDynamicSharedMemorySize, ATTN_SMEM);

    // merged QKV projection (1024 CTAs, warp-specialized bf16x3 tensor GEMM)
    gemm_qkv<<<dim3(32, TOK / 128), 384, GSMEM>>>(hidden, Wq, Wk, Wv, gq, gk, gv);

    // fused RMSNorm + RoPE + split (warp per row)
    rms_rope_split2<<<TOK * 32 / 8, 256>>>(gq, gk, gv, cosb, sinb, qw, kw,
                                           qh, ql, kh, kl, vh, vl);

    // tensor-core causal flash attention
    attn_bf16_kernel<<<dim3(S_ / 128, NH_, B_), 256, ATTN_SMEM>>>(
        qh, ql, kh, kl, vh, vl, gao);

    // output projection
    gemm_nt<<<dim3(H_ / 128, TOK / 128), 384, GSMEM>>>(
        gao, Wo, out, TOK, H_, NH_ * D_);
}

// round 9
// speedup vs baseline: 1.2229x; 1.2229x over previous
#include <cuda_runtime.h>
#include <cuda_bf16.h>
#include <cstdint>

// ---------------------------------------------------------------------------
// Problem constants (B=2, S=2048, H=1024, NH=16, NKV=8, D=128)
// ---------------------------------------------------------------------------
constexpr int B_   = 2;
constexpr int S_   = 2048;
constexpr int H_   = 1024;
constexpr int NH_  = 16;
constexpr int NKV_ = 8;
constexpr int D_   = 128;
constexpr int TOK  = B_ * S_;            // 4096 tokens

// Scratch (device globals; no allocation allowed)
__device__ float g_q [TOK * NH_  * D_];
__device__ float g_k [TOK * NKV_ * D_];
__device__ float g_v [TOK * NKV_ * D_];
__device__ float g_ao[TOK * NH_  * D_];
// bf16 hi/lo split attention operands
__device__ __nv_bfloat16 g_qh[TOK * NH_  * D_], g_ql[TOK * NH_  * D_];
__device__ __nv_bfloat16 g_kh[TOK * NKV_ * D_], g_kl[TOK * NKV_ * D_];
__device__ __nv_bfloat16 g_vh[TOK * NKV_ * D_], g_vl[TOK * NKV_ * D_];

#define DEV_INLINE __device__ __forceinline__

// ---------------------------------------------------------------------------
// helpers
// ---------------------------------------------------------------------------
DEV_INLINE uint32_t cvt_bf16x2(float hi_elem, float lo_elem) {
    uint32_t r;
    asm("cvt.rn.bf16x2.f32 %0, %1, %2;" : "=r"(r) : "f"(hi_elem), "f"(lo_elem));
    return r;
}
// split two fp32 (f0 -> low lane, f1 -> high lane) into bf16 hi-pair + lo-pair
DEV_INLINE void split_pair(float f0, float f1, uint32_t& hiw, uint32_t& low) {
    hiw = cvt_bf16x2(f1, f0);
    float h0 = __uint_as_float(hiw << 16);
    float h1 = __uint_as_float(hiw & 0xFFFF0000u);
    low = cvt_bf16x2(f1 - h1, f0 - h0);
}
DEV_INLINE void ldsm_x4(uint32_t* r, uint32_t addr) {
    asm volatile("ldmatrix.sync.aligned.m8n8.x4.shared.b16 {%0,%1,%2,%3}, [%4];"
                 : "=r"(r[0]), "=r"(r[1]), "=r"(r[2]), "=r"(r[3]) : "r"(addr));
}
DEV_INLINE void ldsm_x4_trans(uint32_t* r, uint32_t addr) {
    asm volatile("ldmatrix.sync.aligned.m8n8.x4.trans.shared.b16 {%0,%1,%2,%3}, [%4];"
                 : "=r"(r[0]), "=r"(r[1]), "=r"(r[2]), "=r"(r[3]) : "r"(addr));
}
DEV_INLINE void mma_bf16(float* c, const uint32_t* a, const uint32_t* b) {
    asm volatile(
        "mma.sync.aligned.m16n8k16.row.col.f32.bf16.bf16.f32 "
        "{%0,%1,%2,%3}, {%4,%5,%6,%7}, {%8,%9}, {%0,%1,%2,%3};"
        : "+f"(c[0]), "+f"(c[1]), "+f"(c[2]), "+f"(c[3])
        : "r"(a[0]), "r"(a[1]), "r"(a[2]), "r"(a[3]), "r"(b[0]), "r"(b[1]));
}
DEV_INLINE uint32_t smem_u32(const void* p) {
    uint32_t a;
    asm("{ .reg .u64 t; cvta.to.shared.u64 t, %1; cvt.u32.u64 %0, t; }"
        : "=r"(a) : "l"(p));
    return a;
}
DEV_INLINE void cp16(uint32_t dst, const void* src) {
    asm volatile("cp.async.cg.shared.global [%0], [%1], 16;"
                 :: "r"(dst), "l"(src) : "memory");
}
DEV_INLINE void cp_commit() { asm volatile("cp.async.commit_group;" ::: "memory"); }
DEV_INLINE void cp_wait1()  { asm volatile("cp.async.wait_group 1;" ::: "memory"); }
DEV_INLINE void cp_wait0()  { asm volatile("cp.async.wait_group 0;" ::: "memory"); }

// ---------------------------------------------------------------------------
// bf16x3 tensor-core NT GEMM — 512 threads / 16 warps (4m x 4n, warp tile
// 32x32), CTA tile 128x128, BK=32, SINGLE-BARRIER software pipeline:
//   iteration c: [ldsm+mma on buf(c&1)] [split+STS chunk c+1 -> buf((c+1)&1)]
//                [LDG chunk c+2 -> regs] [one __syncthreads]
// 3 products: Ah*Bh + Ah*Bl + Al*Bh.
// ---------------------------------------------------------------------------
constexpr int GMATB = 10240;           // 128 * 80 bytes per split tile
constexpr int GBUFB = 4 * GMATB;       // 40960 per double-buffer slot
constexpr int GSMEM = 2 * GBUFB;       // 81920

// split 8 fp32 (2x float4) of A-row piece and B-row piece, store to buffer
DEV_INLINE void split_store(char* bp, uint32_t off, const float4* ra, const float4* rb)
{
    uint32_t h0, l0, h1, l1, h2, l2, h3, l3;
    split_pair(ra[0].x, ra[0].y, h0, l0);
    split_pair(ra[0].z, ra[0].w, h1, l1);
    split_pair(ra[1].x, ra[1].y, h2, l2);
    split_pair(ra[1].z, ra[1].w, h3, l3);
    *reinterpret_cast<uint4*>(bp + off)         = make_uint4(h0, h1, h2, h3);
    *reinterpret_cast<uint4*>(bp + GMATB + off) = make_uint4(l0, l1, l2, l3);
    split_pair(rb[0].x, rb[0].y, h0, l0);
    split_pair(rb[0].z, rb[0].w, h1, l1);
    split_pair(rb[1].x, rb[1].y, h2, l2);
    split_pair(rb[1].z, rb[1].w, h3, l3);
    *reinterpret_cast<uint4*>(bp + 2 * GMATB + off) = make_uint4(h0, h1, h2, h3);
    *reinterpret_cast<uint4*>(bp + 3 * GMATB + off) = make_uint4(l0, l1, l2, l3);
}

DEV_INLINE void gemm_body(const float* __restrict__ A, const float* __restrict__ Bm,
                          float* __restrict__ C, int K, int N, int m0, int n0,
                          char* smem, uint32_t sb)
{
    const int tid  = threadIdx.x;
    const int lane = tid & 31;
    const int wid  = tid >> 5;          // 0..15
    const int wm   = wid & 3;           // 4 m-warps
    const int wn   = wid >> 2;          // 4 n-warps

    // global load mapping: row r, 8-col quarter q
    const int r = tid >> 2;             // 0..127
    const int q = tid & 3;              // quarter (8 f32)
    const uint32_t soff = (uint32_t)r * 80 + (uint32_t)q * 16;
    const float* Arow = A  + (size_t)(m0 + r) * K + q * 8;
    const float* Brow = Bm + (size_t)(n0 + r) * K + q * 8;

    float Cacc[2][4][4];
#pragma unroll
    for (int mi = 0; mi < 2; mi++)
#pragma unroll
        for (int nf = 0; nf < 4; nf++)
#pragma unroll
            for (int e = 0; e < 4; e++) Cacc[mi][nf][e] = 0.f;

    const uint32_t lrow = (uint32_t)(lane & 15);
    const uint32_t lcol = (uint32_t)(lane >> 4) * 16;
    const int NC = K / 32;

    // ---- prologue: chunk 0 -> buf0; prefetch chunk 1 into regs ----
    float4 ra[2], rb[2];
    {
        float4 a0[2], b0[2];
#pragma unroll
        for (int i = 0; i < 2; i++) {
            a0[i] = *reinterpret_cast<const float4*>(Arow + i * 4);
            b0[i] = *reinterpret_cast<const float4*>(Brow + i * 4);
        }
        split_store(smem, soff, a0, b0);
    }
    if (NC > 1) {
#pragma unroll
        for (int i = 0; i < 2; i++) {
            ra[i] = *reinterpret_cast<const float4*>(Arow + 32 + i * 4);
            rb[i] = *reinterpret_cast<const float4*>(Brow + 32 + i * 4);
        }
    }
    __syncthreads();

    for (int c = 0; c < NC; c++) {
        const uint32_t bufs = sb + (c & 1) * GBUFB;

        // ---- compute on buf(c&1) ----
#pragma unroll
        for (int ks = 0; ks < 2; ks++) {
            uint32_t afrag[2][2][4];    // [sel][mi][4]
            uint32_t bfr[2][4][2];      // [sel][nf][2]
#pragma unroll
            for (int sel = 0; sel < 2; sel++) {
#pragma unroll
                for (int mi = 0; mi < 2; mi++) {
                    const uint32_t addr = bufs + (uint32_t)sel * GMATB +
                        ((uint32_t)(wm * 32 + mi * 16) + lrow) * 80 +
                        (uint32_t)ks * 32 + lcol;
                    ldsm_x4(afrag[sel][mi], addr);
                }
#pragma unroll
                for (int ng = 0; ng < 2; ng++) {
                    uint32_t t4[4];
                    const uint32_t addr = bufs + 2 * GMATB + (uint32_t)sel * GMATB +
                        ((uint32_t)(wn * 32 + ng * 16) + lrow) * 80 +
                        (uint32_t)ks * 32 + lcol;
                    ldsm_x4(t4, addr);
                    bfr[sel][ng * 2][0]     = t4[0];
                    bfr[sel][ng * 2][1]     = t4[2];
                    bfr[sel][ng * 2 + 1][0] = t4[1];
                    bfr[sel][ng * 2 + 1][1] = t4[3];
                }
            }
#pragma unroll
            for (int mi = 0; mi < 2; mi++)
#pragma unroll
                for (int nf = 0; nf < 4; nf++)
                    mma_bf16(Cacc[mi][nf], afrag[0][mi], bfr[0][nf]);
#pragma unroll
            for (int mi = 0; mi < 2; mi++)
#pragma unroll
                for (int nf = 0; nf < 4; nf++)
                    mma_bf16(Cacc[mi][nf], afrag[0][mi], bfr[1][nf]);
#pragma unroll
            for (int mi = 0; mi < 2; mi++)
#pragma unroll
                for (int nf = 0; nf < 4; nf++)
                    mma_bf16(Cacc[mi][nf], afrag[1][mi], bfr[0][nf]);
        }

        // ---- split+store chunk c+1 into the other buffer (interleavable) ----
        if (c + 1 < NC) {
            split_store(smem + ((c + 1) & 1) * GBUFB, soff, ra, rb);
            if (c + 2 < NC) {
                const int k0 = (c + 2) * 32;
#pragma unroll
                for (int i = 0; i < 2; i++) {
                    ra[i] = *reinterpret_cast<const float4*>(Arow + k0 + i * 4);
                    rb[i] = *reinterpret_cast<const float4*>(Brow + k0 + i * 4);
                }
            }
        }
        __syncthreads();   // single barrier per chunk
    }

#pragma unroll
    for (int mi = 0; mi < 2; mi++) {
        const int row = m0 + wm * 32 + mi * 16 + (lane >> 2);
#pragma unroll
        for (int nf = 0; nf < 4; nf++) {
            const int col = n0 + wn * 32 + nf * 8 + (lane & 3) * 2;
            *reinterpret_cast<float2*>(C + (size_t)row * N + col) =
                make_float2(Cacc[mi][nf][0], Cacc[mi][nf][1]);
            *reinterpret_cast<float2*>(C + (size_t)(row + 8) * N + col) =
                make_float2(Cacc[mi][nf][2], Cacc[mi][nf][3]);
        }
    }
}

// Merged QKV projection: grid (32 n-tiles routed, 32 m-tiles)
__global__ void __launch_bounds__(512, 1)
gemm_qkv(const float* __restrict__ A,
         const float* __restrict__ Wq, const float* __restrict__ Wk,
         const float* __restrict__ Wv,
         float* __restrict__ q, float* __restrict__ k, float* __restrict__ v)
{
    extern __shared__ char smem[];
    const uint32_t sb = smem_u32(smem);
    const int bx = blockIdx.x;
    const int m0 = blockIdx.y * 128;

    const float* Bm; float* C; int N; int n0;
    if (bx < 16)      { Bm = Wq; C = q; N = NH_ * D_;  n0 = bx * 128; }
    else if (bx < 24) { Bm = Wk; C = k; N = NKV_ * D_; n0 = (bx - 16) * 128; }
    else              { Bm = Wv; C = v; N = NKV_ * D_; n0 = (bx - 24) * 128; }

    gemm_body(A, Bm, C, H_, N, m0, n0, smem, sb);
}

// Generic GEMM (output projection)
__global__ void __launch_bounds__(512, 1)
gemm_nt(const float* __restrict__ A, const float* __restrict__ Bm,
        float* __restrict__ C, int M, int N, int K)
{
    extern __shared__ char smem[];
    const uint32_t sb = smem_u32(smem);
    gemm_body(A, Bm, C, K, N, blockIdx.y * 128, blockIdx.x * 128, smem, sb);
}

// ---------------------------------------------------------------------------
// Fused RMSNorm + RoPE + bf16 hi/lo split. Warp-per-row (D=128, 4 els/lane).
// rows = TOK * 32 (hh: 0-15 q, 16-23 k, 24-31 v). 256-thread blocks, 8 rows.
// ---------------------------------------------------------------------------
__global__ void __launch_bounds__(256)
rms_rope_split2(const float* __restrict__ qbuf, const float* __restrict__ kbuf,
                const float* __restrict__ vbuf,
                const float* __restrict__ cosb, const float* __restrict__ sinb,
                const float* __restrict__ qw,   const float* __restrict__ kw,
                __nv_bfloat16* __restrict__ qh, __nv_bfloat16* __restrict__ ql,
                __nv_bfloat16* __restrict__ kh, __nv_bfloat16* __restrict__ kl,
                __nv_bfloat16* __restrict__ vh, __nv_bfloat16* __restrict__ vl)
{
    const int rrow = blockIdx.x * 8 + (threadIdx.x >> 5);
    const int l    = threadIdx.x & 31;
    const int t    = rrow >> 5;
    const int hh   = rrow & 31;

    if (hh >= 24) {                      // v: split only
        const size_t base = (size_t)t * (NKV_ * D_) + (hh - 24) * D_ + l * 4;
        const float4 x = *reinterpret_cast<const float4*>(vbuf + base);
        uint32_t h0, l0, h1, l1;
        split_pair(x.x, x.y, h0, l0);
        split_pair(x.z, x.w, h1, l1);
        *reinterpret_cast<uint2*>(vh + base) = make_uint2(h0, h1);
        *reinterpret_cast<uint2*>(vl + base) = make_uint2(l0, l1);
        return;
    }

    const float* src; const float* w;
    __nv_bfloat16 *oh, *ol;
    size_t base;
    if (hh < 16) {
        base = (size_t)t * (NH_ * D_) + hh * D_ + l * 4;
        src = qbuf; w = qw; oh = qh; ol = ql;
    } else {
        base = (size_t)t * (NKV_ * D_) + (hh - 16) * D_ + l * 4;
        src = kbuf; w = kw; oh = kh; ol = kl;
    }

    const float4 x = *reinterpret_cast<const float4*>(src + base);
    float ss = x.x * x.x + x.y * x.y + x.z * x.z + x.w * x.w;
#pragma unroll
    for (int off = 16; off >= 1; off >>= 1) ss += __shfl_xor_sync(0xffffffffu, ss, off);
    const float inv = rsqrtf(ss * (1.0f / 128.0f) + 1e-6f);

    const float4 wv = *reinterpret_cast<const float4*>(w + l * 4);
    const float4 cv = *reinterpret_cast<const float4*>(cosb + (size_t)t * D_ + l * 4);
    const float4 sv = *reinterpret_cast<const float4*>(sinb + (size_t)t * D_ + l * 4);

    const float z0 = x.x * wv.x, z1 = x.y * wv.y, z2 = x.z * wv.z, z3 = x.w * wv.w;
    const float p0 = __shfl_xor_sync(0xffffffffu, z0, 16);
    const float p1 = __shfl_xor_sync(0xffffffffu, z1, 16);
    const float p2 = __shfl_xor_sync(0xffffffffu, z2, 16);
    const float p3 = __shfl_xor_sync(0xffffffffu, z3, 16);
    const float sgn = (l < 16) ? -1.f : 1.f;

    const float y0 = (z0 * cv.x + sgn * p0 * sv.x) * inv;
    const float y1 = (z1 * cv.y + sgn * p1 * sv.y) * inv;
    const float y2 = (z2 * cv.z + sgn * p2 * sv.z) * inv;
    const float y3 = (z3 * cv.w + sgn * p3 * sv.w) * inv;

    uint32_t h0, l0w, h1, l1w;
    split_pair(y0, y1, h0, l0w);
    split_pair(y2, y3, h1, l1w);
    *reinterpret_cast<uint2*>(oh + base) = make_uint2(h0, h1);
    *reinterpret_cast<uint2*>(ol + base) = make_uint2(l0w, l1w);
}

// ---------------------------------------------------------------------------
// Tensor-core flash attention (bf16x3, causal, GQA n_rep=2). Round-4 proven.
// BQ=128, BKV=64, D=128. 256 threads = 8 warps, warp w -> q rows w*16..+15.
// ---------------------------------------------------------------------------
constexpr int AQ_BYTES  = 128 * 272;                 // 34816
constexpr int AKV_BYTES = 64 * 272;                  // 17408
constexpr int ABUF0     = 2 * AQ_BYTES;              // 69632
constexpr int ABUFSZ    = 4 * AKV_BYTES;             // 69632
constexpr int ATTN_SMEM = ABUF0 + 2 * ABUFSZ;        // 208896

__global__ void __launch_bounds__(256, 1)
attn_bf16_kernel(const __nv_bfloat16* __restrict__ qh, const __nv_bfloat16* __restrict__ ql,
                 const __nv_bfloat16* __restrict__ kh, const __nv_bfloat16* __restrict__ kl,
                 const __nv_bfloat16* __restrict__ vh, const __nv_bfloat16* __restrict__ vl,
                 float* __restrict__ ao)
{
    extern __shared__ char smem[];
    const uint32_t sb = smem_u32(smem);

    const int tid  = threadIdx.x;
    const int lane = tid & 31;
    const int w    = tid >> 5;
    const int qi   = gridDim.x - 1 - blockIdx.x;
    const int h    = blockIdx.y;
    const int b    = blockIdx.z;
    const int kvh  = h >> 1;

#pragma unroll
    for (int i = 0; i < 8; i++) {
        const int idx = tid + i * 256;
        const int row = idx >> 4, ch = idx & 15;
        const size_t g = ((size_t)(b * S_) + qi * 128 + row) * (NH_ * D_) + h * D_ + ch * 8;
        cp16(sb + row * 272 + ch * 16,            qh + g);
        cp16(sb + AQ_BYTES + row * 272 + ch * 16, ql + g);
    }
    {
        const uint32_t buf = sb + ABUF0;
#pragma unroll
        for (int i = 0; i < 4; i++) {
            const int idx = tid + i * 256;
            const int row = idx >> 4, ch = idx & 15;
            const size_t g = ((size_t)(b * S_) + row) * (NKV_ * D_) + kvh * D_ + ch * 8;
            const uint32_t so = buf + row * 272 + ch * 16;
            cp16(so,                 kh + g);
            cp16(so + AKV_BYTES,     kl + g);
            cp16(so + 2 * AKV_BYTES, vh + g);
            cp16(so + 3 * AKV_BYTES, vl + g);
        }
    }
    cp_commit();

    float oacc[16][4];
#pragma unroll
    for (int i = 0; i < 16; i++)
#pragma unroll
        for (int e = 0; e < 4; e++) oacc[i][e] = 0.f;
    float m_i[2] = {-1e30f, -1e30f};
    float l_i[2] = {0.f, 0.f};

    const uint32_t lrow16 = (uint32_t)(lane & 15);
    const uint32_t lhalf  = (uint32_t)(lane >> 4) * 16;
    const int jmax = 2 * qi + 1;

    for (int jb = 0; jb <= jmax; jb++) {
        if (jb < jmax) {
            const uint32_t buf = sb + ABUF0 + ((jb + 1) & 1) * ABUFSZ;
#pragma unroll
            for (int i = 0; i < 4; i++) {
                const int idx = tid + i * 256;
                const int row = idx >> 4, ch = idx & 15;
                const size_t g = ((size_t)(b * S_) + (jb + 1) * 64 + row) * (NKV_ * D_) +
                                 kvh * D_ + ch * 8;
                const uint32_t so = buf + row * 272 + ch * 16;
                cp16(so,                 kh + g);
                cp16(so + AKV_BYTES,     kl + g);
                cp16(so + 2 * AKV_BYTES, vh + g);
                cp16(so + 3 * AKV_BYTES, vl + g);
            }
            cp_commit();
            cp_wait1();
        } else {
            cp_wait0();
        }
        __syncthreads();

        const uint32_t kb = sb + ABUF0 + (jb & 1) * ABUFSZ;
        const bool skip = (jb * 64) > (qi * 128 + w * 16 + 15);

        if (!skip) {
            float sacc[8][4];
#pragma unroll
            for (int i = 0; i < 8; i++)
#pragma unroll
                for (int e = 0; e < 4; e++) sacc[i][e] = 0.f;

            const uint32_t qbase = sb + ((uint32_t)(w * 16) + lrow16) * 272 + lhalf;
#pragma unroll
            for (int ks = 0; ks < 8; ks++) {
                uint32_t ahi[4], alo[4];
                ldsm_x4(ahi, qbase + ks * 32);
                ldsm_x4(alo, qbase + AQ_BYTES + ks * 32);
#pragma unroll
                for (int ng = 0; ng < 4; ng++) {
                    uint32_t t[4], u[4];
                    const uint32_t ka = kb + ((uint32_t)(ng * 16) + lrow16) * 272 + ks * 32 + lhalf;
                    ldsm_x4(t, ka);
                    ldsm_x4(u, ka + AKV_BYTES);
                    uint32_t bh0[2] = {t[0], t[2]}, bh1[2] = {t[1], t[3]};
                    uint32_t bl0[2] = {u[0], u[2]}, bl1[2] = {u[1], u[3]};
                    mma_bf16(sacc[ng * 2],     ahi, bh0);
                    mma_bf16(sacc[ng * 2 + 1], ahi, bh1);
                    mma_bf16(sacc[ng * 2],     ahi, bl0);
                    mma_bf16(sacc[ng * 2 + 1], ahi, bl1);
                    mma_bf16(sacc[ng * 2],     alo, bh0);
                    mma_bf16(sacc[ng * 2 + 1], alo, bh1);
                }
            }

            const float sc = 0.088388347648318447f;
            const bool domask = (jb * 64 + 63) > (qi * 128 + w * 16);
#pragma unroll
            for (int nf = 0; nf < 8; nf++)
#pragma unroll
                for (int e = 0; e < 4; e++) {
                    float s = sacc[nf][e] * sc;
                    if (domask) {
                        const int col = jb * 64 + nf * 8 + ((lane & 3) << 1) + (e & 1);
                        const int row = qi * 128 + w * 16 + (lane >> 2) + ((e >> 1) << 3);
                        if (col > row) s = -1e30f;
                    }
                    sacc[nf][e] = s;
                }

#pragma unroll
            for (int r2 = 0; r2 < 2; r2++) {
                float mx = -1e30f;
#pragma unroll
                for (int nf = 0; nf < 8; nf++)
                    mx = fmaxf(mx, fmaxf(sacc[nf][2 * r2], sacc[nf][2 * r2 + 1]));
                mx = fmaxf(mx, __shfl_xor_sync(0xffffffffu, mx, 1));
                mx = fmaxf(mx, __shfl_xor_sync(0xffffffffu, mx, 2));
                const float mn = fmaxf(m_i[r2], mx);
                const float alpha = __expf(m_i[r2] - mn);
                m_i[r2] = mn;
                float rs = 0.f;
#pragma unroll
                for (int nf = 0; nf < 8; nf++) {
                    float p0 = __expf(sacc[nf][2 * r2]     - mn);
                    float p1 = __expf(sacc[nf][2 * r2 + 1] - mn);
                    sacc[nf][2 * r2]     = p0;
                    sacc[nf][2 * r2 + 1] = p1;
                    rs += p0 + p1;
                }
                rs += __shfl_xor_sync(0xffffffffu, rs, 1);
                rs += __shfl_xor_sync(0xffffffffu, rs, 2);
                l_i[r2] = l_i[r2] * alpha + rs;
#pragma unroll
                for (int ndf = 0; ndf < 16; ndf++) {
                    oacc[ndf][2 * r2]     *= alpha;
                    oacc[ndf][2 * r2 + 1] *= alpha;
                }
            }

#pragma unroll
            for (int kk = 0; kk < 4; kk++) {
                uint32_t phi[4], plo[4];
                split_pair(sacc[2 * kk][0],     sacc[2 * kk][1],     phi[0], plo[0]);
                split_pair(sacc[2 * kk][2],     sacc[2 * kk][3],     phi[1], plo[1]);
                split_pair(sacc[2 * kk + 1][0], sacc[2 * kk + 1][1], phi[2], plo[2]);
                split_pair(sacc[2 * kk + 1][2], sacc[2 * kk + 1][3], phi[3], plo[3]);
#pragma unroll
                for (int ndg = 0; ndg < 8; ndg++) {
                    uint32_t t[4], u[4];
                    const uint32_t va = kb + 2 * AKV_BYTES +
                        ((uint32_t)(kk * 16) + lrow16) * 272 + ndg * 32 + lhalf;
                    ldsm_x4_trans(t, va);
                    ldsm_x4_trans(u, va + AKV_BYTES);
                    uint32_t bh0[2] = {t[0], t[1]}, bh1[2] = {t[2], t[3]};
                    uint32_t bl0[2] = {u[0], u[1]}, bl1[2] = {u[2], u[3]};
                    mma_bf16(oacc[ndg * 2],     phi, bh0);
                    mma_bf16(oacc[ndg * 2 + 1], phi, bh1);
                    mma_bf16(oacc[ndg * 2],     phi, bl0);
                    mma_bf16(oacc[ndg * 2 + 1], phi, bl1);
                    mma_bf16(oacc[ndg * 2],     plo, bh0);
                    mma_bf16(oacc[ndg * 2 + 1], plo, bh1);
                }
            }
        }
        __syncthreads();
    }

    const float i0 = 1.0f / l_i[0];
    const float i1 = 1.0f / l_i[1];
    const int row0 = qi * 128 + w * 16 + (lane >> 2);
    const size_t base0 = ((size_t)(b * S_) + row0) * (NH_ * D_) + h * D_ + (lane & 3) * 2;
    const size_t base1 = base0 + (size_t)8 * (NH_ * D_);
#pragma unroll
    for (int ndf = 0; ndf < 16; ndf++) {
        *reinterpret_cast<float2*>(ao + base0 + ndf * 8) =
            make_float2(oacc[ndf][0] * i0, oacc[ndf][1] * i0);
        *reinterpret_cast<float2*>(ao + base1 + ndf * 8) =
            make_float2(oacc[ndf][2] * i1, oacc[ndf][3] * i1);
    }
}

// ---------------------------------------------------------------------------
// Launch
// ---------------------------------------------------------------------------
extern "C" void kernel_launch(void* const* d_in, const int* in_sizes, int n_in,
                              void* d_out, int out_size)
{
    const float* hidden = (const float*)d_in[0];
    const float* cosb   = (const float*)d_in[1];
    const float* sinb   = (const float*)d_in[2];
    const float* Wq     = (const float*)d_in[3];
    const float* Wk     = (const float*)d_in[4];
    const float* Wv     = (const float*)d_in[5];
    const float* Wo     = (const float*)d_in[6];
    const float* qw     = (const float*)d_in[7];
    const float* kw     = (const float*)d_in[8];
    float* out = (float*)d_out;

    float *gq, *gk, *gv, *gao;
    cudaGetSymbolAddress((void**)&gq,  g_q);
    cudaGetSymbolAddress((void**)&gk,  g_k);
    cudaGetSymbolAddress((void**)&gv,  g_v);
    cudaGetSymbolAddress((void**)&gao, g_ao);
    __nv_bfloat16 *qh, *ql, *kh, *kl, *vh, *vl;
    cudaGetSymbolAddress((void**)&qh, g_qh);
    cudaGetSymbolAddress((void**)&ql, g_ql);
    cudaGetSymbolAddress((void**)&kh, g_kh);
    cudaGetSymbolAddress((void**)&kl, g_kl);
    cudaGetSymbolAddress((void**)&vh, g_vh);
    cudaGetSymbolAddress((void**)&vl, g_vl);

    cudaFuncSetAttribute((const void*)gemm_qkv,
                         cudaFuncAttributeMaxDynamicSharedMemorySize, GSMEM);
    cudaFuncSetAttribute((const void*)gemm_nt,
                         cudaFuncAttributeMaxDynamicSharedMemorySize, GSMEM);
    cudaFuncSetAttribute((const void*)attn_bf16_kernel,
                         cudaFuncAttributeMaxDynamicSharedMemorySize, ATTN_SMEM);

    // merged QKV projection (1024 CTAs, pipelined bf16x3 tensor GEMM)
    gemm_qkv<<<dim3(32, TOK / 128), 512, GSMEM>>>(hidden, Wq, Wk, Wv, gq, gk, gv);

    // fused RMSNorm + RoPE + split (warp per row)
    rms_rope_split2<<<TOK * 32 / 8, 256>>>(gq, gk, gv, cosb, sinb, qw, kw,
                                           qh, ql, kh, kl, vh, vl);

    // tensor-core causal flash attention
    attn_bf16_kernel<<<dim3(S_ / 128, NH_, B_), 256, ATTN_SMEM>>>(
        qh, ql, kh, kl, vh, vl, gao);

    // output projection
    gemm_nt<<<dim3(H_ / 128, TOK / 128), 512, GSMEM>>>(
        gao, Wo, out, TOK, H_, NH_ * D_);
}

// round 10
// speedup vs baseline: 1.2329x; 1.0082x over previous
#include <cuda_runtime.h>
#include <cuda_bf16.h>
#include <cstdint>

// ---------------------------------------------------------------------------
// Problem constants (B=2, S=2048, H=1024, NH=16, NKV=8, D=128)
// ---------------------------------------------------------------------------
constexpr int B_   = 2;
constexpr int S_   = 2048;
constexpr int H_   = 1024;
constexpr int NH_  = 16;
constexpr int NKV_ = 8;
constexpr int D_   = 128;
constexpr int TOK  = B_ * S_;            // 4096 tokens

// Scratch (device globals; no allocation allowed)
__device__ float g_q [TOK * NH_  * D_];
__device__ float g_k [TOK * NKV_ * D_];
__device__ float g_v [TOK * NKV_ * D_];
__device__ float g_ao[TOK * NH_  * D_];
// bf16 hi/lo split attention operands
__device__ __nv_bfloat16 g_qh[TOK * NH_  * D_], g_ql[TOK * NH_  * D_];
__device__ __nv_bfloat16 g_kh[TOK * NKV_ * D_], g_kl[TOK * NKV_ * D_];
__device__ __nv_bfloat16 g_vh[TOK * NKV_ * D_], g_vl[TOK * NKV_ * D_];

#define DEV_INLINE __device__ __forceinline__

// ---------------------------------------------------------------------------
// helpers
// ---------------------------------------------------------------------------
DEV_INLINE uint32_t cvt_bf16x2(float hi_elem, float lo_elem) {
    uint32_t r;
    asm("cvt.rn.bf16x2.f32 %0, %1, %2;" : "=r"(r) : "f"(hi_elem), "f"(lo_elem));
    return r;
}
// split two fp32 (f0 -> low lane, f1 -> high lane) into bf16 hi-pair + lo-pair
DEV_INLINE void split_pair(float f0, float f1, uint32_t& hiw, uint32_t& low) {
    hiw = cvt_bf16x2(f1, f0);
    float h0 = __uint_as_float(hiw << 16);
    float h1 = __uint_as_float(hiw & 0xFFFF0000u);
    low = cvt_bf16x2(f1 - h1, f0 - h0);
}
DEV_INLINE void ldsm_x4(uint32_t* r, uint32_t addr) {
    asm volatile("ldmatrix.sync.aligned.m8n8.x4.shared.b16 {%0,%1,%2,%3}, [%4];"
                 : "=r"(r[0]), "=r"(r[1]), "=r"(r[2]), "=r"(r[3]) : "r"(addr));
}
DEV_INLINE void ldsm_x4_trans(uint32_t* r, uint32_t addr) {
    asm volatile("ldmatrix.sync.aligned.m8n8.x4.trans.shared.b16 {%0,%1,%2,%3}, [%4];"
                 : "=r"(r[0]), "=r"(r[1]), "=r"(r[2]), "=r"(r[3]) : "r"(addr));
}
DEV_INLINE void mma_bf16(float* c, const uint32_t* a, const uint32_t* b) {
    asm volatile(
        "mma.sync.aligned.m16n8k16.row.col.f32.bf16.bf16.f32 "
        "{%0,%1,%2,%3}, {%4,%5,%6,%7}, {%8,%9}, {%0,%1,%2,%3};"
        : "+f"(c[0]), "+f"(c[1]), "+f"(c[2]), "+f"(c[3])
        : "r"(a[0]), "r"(a[1]), "r"(a[2]), "r"(a[3]), "r"(b[0]), "r"(b[1]));
}
DEV_INLINE uint32_t smem_u32(const void* p) {
    uint32_t a;
    asm("{ .reg .u64 t; cvta.to.shared.u64 t, %1; cvt.u32.u64 %0, t; }"
        : "=r"(a) : "l"(p));
    return a;
}
DEV_INLINE void cp16(uint32_t dst, const void* src) {
    asm volatile("cp.async.cg.shared.global [%0], [%1], 16;"
                 :: "r"(dst), "l"(src) : "memory");
}
DEV_INLINE void cp_commit() { asm volatile("cp.async.commit_group;" ::: "memory"); }
DEV_INLINE void cp_wait1()  { asm volatile("cp.async.wait_group 1;" ::: "memory"); }
DEV_INLINE void cp_wait0()  { asm volatile("cp.async.wait_group 0;" ::: "memory"); }

// ---------------------------------------------------------------------------
// bf16x3 tensor-core NT GEMM — 512 threads / 16 warps (4m x 4n, warp tile
// 32x32), CTA tile 128x128, BK=32, single-barrier pipeline + WARP STAGGERING:
//   - ks order per warp:  ks = ksi ^ (wid & 1)
//   - split/STS placement: warps with (wid & 2) do it BEFORE their mma block
// 3 products: Ah*Bh + Ah*Bl + Al*Bh.
// ---------------------------------------------------------------------------
constexpr int GMATB = 10240;           // 128 * 80 bytes per split tile
constexpr int GBUFB = 4 * GMATB;       // 40960 per double-buffer slot
constexpr int GSMEM = 2 * GBUFB;       // 81920

// split 8 fp32 (2x float4) of A-row piece and B-row piece, store to buffer
DEV_INLINE void split_store(char* bp, uint32_t off, const float4* ra, const float4* rb)
{
    uint32_t h0, l0, h1, l1, h2, l2, h3, l3;
    split_pair(ra[0].x, ra[0].y, h0, l0);
    split_pair(ra[0].z, ra[0].w, h1, l1);
    split_pair(ra[1].x, ra[1].y, h2, l2);
    split_pair(ra[1].z, ra[1].w, h3, l3);
    *reinterpret_cast<uint4*>(bp + off)         = make_uint4(h0, h1, h2, h3);
    *reinterpret_cast<uint4*>(bp + GMATB + off) = make_uint4(l0, l1, l2, l3);
    split_pair(rb[0].x, rb[0].y, h0, l0);
    split_pair(rb[0].z, rb[0].w, h1, l1);
    split_pair(rb[1].x, rb[1].y, h2, l2);
    split_pair(rb[1].z, rb[1].w, h3, l3);
    *reinterpret_cast<uint4*>(bp + 2 * GMATB + off) = make_uint4(h0, h1, h2, h3);
    *reinterpret_cast<uint4*>(bp + 3 * GMATB + off) = make_uint4(l0, l1, l2, l3);
}

DEV_INLINE void gemm_body(const float* __restrict__ A, const float* __restrict__ Bm,
                          float* __restrict__ C, int K, int N, int m0, int n0,
                          char* smem, uint32_t sb)
{
    const int tid  = threadIdx.x;
    const int lane = tid & 31;
    const int wid  = tid >> 5;          // 0..15
    const int wm   = wid & 3;           // 4 m-warps
    const int wn   = wid >> 2;          // 4 n-warps
    const int  ks0   = wid & 1;               // ks rotation
    const bool early = (wid & 2) != 0;        // split/STS before mma?

    // global load mapping: row r, 8-col quarter q
    const int r = tid >> 2;             // 0..127
    const int q = tid & 3;              // quarter (8 f32)
    const uint32_t soff = (uint32_t)r * 80 + (uint32_t)q * 16;
    const float* Arow = A  + (size_t)(m0 + r) * K + q * 8;
    const float* Brow = Bm + (size_t)(n0 + r) * K + q * 8;

    float Cacc[2][4][4];
#pragma unroll
    for (int mi = 0; mi < 2; mi++)
#pragma unroll
        for (int nf = 0; nf < 4; nf++)
#pragma unroll
            for (int e = 0; e < 4; e++) Cacc[mi][nf][e] = 0.f;

    const uint32_t lrow = (uint32_t)(lane & 15);
    const uint32_t lcol = (uint32_t)(lane >> 4) * 16;
    const int NC = K / 32;

    // ---- prologue: chunk 0 -> buf0; prefetch chunk 1 into regs ----
    float4 ra[2], rb[2];
    {
        float4 a0[2], b0[2];
#pragma unroll
        for (int i = 0; i < 2; i++) {
            a0[i] = *reinterpret_cast<const float4*>(Arow + i * 4);
            b0[i] = *reinterpret_cast<const float4*>(Brow + i * 4);
        }
        split_store(smem, soff, a0, b0);
    }
    if (NC > 1) {
#pragma unroll
        for (int i = 0; i < 2; i++) {
            ra[i] = *reinterpret_cast<const float4*>(Arow + 32 + i * 4);
            rb[i] = *reinterpret_cast<const float4*>(Brow + 32 + i * 4);
        }
    }
    __syncthreads();

    for (int c = 0; c < NC; c++) {
        const uint32_t bufs = sb + (c & 1) * GBUFB;

        // ---- early warps: split+store chunk c+1, prefetch c+2 ----
        if (early && c + 1 < NC) {
            split_store(smem + ((c + 1) & 1) * GBUFB, soff, ra, rb);
            if (c + 2 < NC) {
                const int k0 = (c + 2) * 32;
#pragma unroll
                for (int i = 0; i < 2; i++) {
                    ra[i] = *reinterpret_cast<const float4*>(Arow + k0 + i * 4);
                    rb[i] = *reinterpret_cast<const float4*>(Brow + k0 + i * 4);
                }
            }
        }

        // ---- compute on buf(c&1), per-warp ks rotation ----
#pragma unroll
        for (int ksi = 0; ksi < 2; ksi++) {
            const int ks = ksi ^ ks0;
            uint32_t afrag[2][2][4];    // [sel][mi][4]
            uint32_t bfr[2][4][2];      // [sel][nf][2]
#pragma unroll
            for (int sel = 0; sel < 2; sel++) {
#pragma unroll
                for (int mi = 0; mi < 2; mi++) {
                    const uint32_t addr = bufs + (uint32_t)sel * GMATB +
                        ((uint32_t)(wm * 32 + mi * 16) + lrow) * 80 +
                        (uint32_t)ks * 32 + lcol;
                    ldsm_x4(afrag[sel][mi], addr);
                }
#pragma unroll
                for (int ng = 0; ng < 2; ng++) {
                    uint32_t t4[4];
                    const uint32_t addr = bufs + 2 * GMATB + (uint32_t)sel * GMATB +
                        ((uint32_t)(wn * 32 + ng * 16) + lrow) * 80 +
                        (uint32_t)ks * 32 + lcol;
                    ldsm_x4(t4, addr);
                    bfr[sel][ng * 2][0]     = t4[0];
                    bfr[sel][ng * 2][1]     = t4[2];
                    bfr[sel][ng * 2 + 1][0] = t4[1];
                    bfr[sel][ng * 2 + 1][1] = t4[3];
                }
            }
#pragma unroll
            for (int mi = 0; mi < 2; mi++)
#pragma unroll
                for (int nf = 0; nf < 4; nf++)
                    mma_bf16(Cacc[mi][nf], afrag[0][mi], bfr[0][nf]);
#pragma unroll
            for (int mi = 0; mi < 2; mi++)
#pragma unroll
                for (int nf = 0; nf < 4; nf++)
                    mma_bf16(Cacc[mi][nf], afrag[0][mi], bfr[1][nf]);
#pragma unroll
            for (int mi = 0; mi < 2; mi++)
#pragma unroll
                for (int nf = 0; nf < 4; nf++)
                    mma_bf16(Cacc[mi][nf], afrag[1][mi], bfr[0][nf]);
        }

        // ---- late warps: split+store chunk c+1, prefetch c+2 ----
        if (!early && c + 1 < NC) {
            split_store(smem + ((c + 1) & 1) * GBUFB, soff, ra, rb);
            if (c + 2 < NC) {
                const int k0 = (c + 2) * 32;
#pragma unroll
                for (int i = 0; i < 2; i++) {
                    ra[i] = *reinterpret_cast<const float4*>(Arow + k0 + i * 4);
                    rb[i] = *reinterpret_cast<const float4*>(Brow + k0 + i * 4);
                }
            }
        }
        __syncthreads();   // single barrier per chunk
    }

#pragma unroll
    for (int mi = 0; mi < 2; mi++) {
        const int row = m0 + wm * 32 + mi * 16 + (lane >> 2);
#pragma unroll
        for (int nf = 0; nf < 4; nf++) {
            const int col = n0 + wn * 32 + nf * 8 + (lane & 3) * 2;
            *reinterpret_cast<float2*>(C + (size_t)row * N + col) =
                make_float2(Cacc[mi][nf][0], Cacc[mi][nf][1]);
            *reinterpret_cast<float2*>(C + (size_t)(row + 8) * N + col) =
                make_float2(Cacc[mi][nf][2], Cacc[mi][nf][3]);
        }
    }
}

// Merged QKV projection: grid (32 n-tiles routed, 32 m-tiles)
__global__ void __launch_bounds__(512, 1)
gemm_qkv(const float* __restrict__ A,
         const float* __restrict__ Wq, const float* __restrict__ Wk,
         const float* __restrict__ Wv,
         float* __restrict__ q, float* __restrict__ k, float* __restrict__ v)
{
    extern __shared__ char smem[];
    const uint32_t sb = smem_u32(smem);
    const int bx = blockIdx.x;
    const int m0 = blockIdx.y * 128;

    const float* Bm; float* C; int N; int n0;
    if (bx < 16)      { Bm = Wq; C = q; N = NH_ * D_;  n0 = bx * 128; }
    else if (bx < 24) { Bm = Wk; C = k; N = NKV_ * D_; n0 = (bx - 16) * 128; }
    else              { Bm = Wv; C = v; N = NKV_ * D_; n0 = (bx - 24) * 128; }

    gemm_body(A, Bm, C, H_, N, m0, n0, smem, sb);
}

// Generic GEMM (output projection)
__global__ void __launch_bounds__(512, 1)
gemm_nt(const float* __restrict__ A, const float* __restrict__ Bm,
        float* __restrict__ C, int M, int N, int K)
{
    extern __shared__ char smem[];
    const uint32_t sb = smem_u32(smem);
    gemm_body(A, Bm, C, K, N, blockIdx.y * 128, blockIdx.x * 128, smem, sb);
}

// ---------------------------------------------------------------------------
// Fused RMSNorm + RoPE + bf16 hi/lo split. Warp-per-row (D=128, 4 els/lane).
// rows = TOK * 32 (hh: 0-15 q, 16-23 k, 24-31 v). 256-thread blocks, 8 rows.
// ---------------------------------------------------------------------------
__global__ void __launch_bounds__(256)
rms_rope_split2(const float* __restrict__ qbuf, const float* __restrict__ kbuf,
                const float* __restrict__ vbuf,
                const float* __restrict__ cosb, const float* __restrict__ sinb,
                const float* __restrict__ qw,   const float* __restrict__ kw,
                __nv_bfloat16* __restrict__ qh, __nv_bfloat16* __restrict__ ql,
                __nv_bfloat16* __restrict__ kh, __nv_bfloat16* __restrict__ kl,
                __nv_bfloat16* __restrict__ vh, __nv_bfloat16* __restrict__ vl)
{
    const int rrow = blockIdx.x * 8 + (threadIdx.x >> 5);
    const int l    = threadIdx.x & 31;
    const int t    = rrow >> 5;
    const int hh   = rrow & 31;

    if (hh >= 24) {                      // v: split only
        const size_t base = (size_t)t * (NKV_ * D_) + (hh - 24) * D_ + l * 4;
        const float4 x = *reinterpret_cast<const float4*>(vbuf + base);
        uint32_t h0, l0, h1, l1;
        split_pair(x.x, x.y, h0, l0);
        split_pair(x.z, x.w, h1, l1);
        *reinterpret_cast<uint2*>(vh + base) = make_uint2(h0, h1);
        *reinterpret_cast<uint2*>(vl + base) = make_uint2(l0, l1);
        return;
    }

    const float* src; const float* w;
    __nv_bfloat16 *oh, *ol;
    size_t base;
    if (hh < 16) {
        base = (size_t)t * (NH_ * D_) + hh * D_ + l * 4;
        src = qbuf; w = qw; oh = qh; ol = ql;
    } else {
        base = (size_t)t * (NKV_ * D_) + (hh - 16) * D_ + l * 4;
        src = kbuf; w = kw; oh = kh; ol = kl;
    }

    const float4 x = *reinterpret_cast<const float4*>(src + base);
    float ss = x.x * x.x + x.y * x.y + x.z * x.z + x.w * x.w;
#pragma unroll
    for (int off = 16; off >= 1; off >>= 1) ss += __shfl_xor_sync(0xffffffffu, ss, off);
    const float inv = rsqrtf(ss * (1.0f / 128.0f) + 1e-6f);

    const float4 wv = *reinterpret_cast<const float4*>(w + l * 4);
    const float4 cv = *reinterpret_cast<const float4*>(cosb + (size_t)t * D_ + l * 4);
    const float4 sv = *reinterpret_cast<const float4*>(sinb + (size_t)t * D_ + l * 4);

    const float z0 = x.x * wv.x, z1 = x.y * wv.y, z2 = x.z * wv.z, z3 = x.w * wv.w;
    const float p0 = __shfl_xor_sync(0xffffffffu, z0, 16);
    const float p1 = __shfl_xor_sync(0xffffffffu, z1, 16);
    const float p2 = __shfl_xor_sync(0xffffffffu, z2, 16);
    const float p3 = __shfl_xor_sync(0xffffffffu, z3, 16);
    const float sgn = (l < 16) ? -1.f : 1.f;

    const float y0 = (z0 * cv.x + sgn * p0 * sv.x) * inv;
    const float y1 = (z1 * cv.y + sgn * p1 * sv.y) * inv;
    const float y2 = (z2 * cv.z + sgn * p2 * sv.z) * inv;
    const float y3 = (z3 * cv.w + sgn * p3 * sv.w) * inv;

    uint32_t h0, l0w, h1, l1w;
    split_pair(y0, y1, h0, l0w);
    split_pair(y2, y3, h1, l1w);
    *reinterpret_cast<uint2*>(oh + base) = make_uint2(h0, h1);
    *reinterpret_cast<uint2*>(ol + base) = make_uint2(l0w, l1w);
}

// ---------------------------------------------------------------------------
// Tensor-core flash attention (bf16x3, causal, GQA n_rep=2). Round-4 proven.
// BQ=128, BKV=64, D=128. 256 threads = 8 warps, warp w -> q rows w*16..+15.
// ---------------------------------------------------------------------------
constexpr int AQ_BYTES  = 128 * 272;                 // 34816
constexpr int AKV_BYTES = 64 * 272;                  // 17408
constexpr int ABUF0     = 2 * AQ_BYTES;              // 69632
constexpr int ABUFSZ    = 4 * AKV_BYTES;             // 69632
constexpr int ATTN_SMEM = ABUF0 + 2 * ABUFSZ;        // 208896

__global__ void __launch_bounds__(256, 1)
attn_bf16_kernel(const __nv_bfloat16* __restrict__ qh, const __nv_bfloat16* __restrict__ ql,
                 const __nv_bfloat16* __restrict__ kh, const __nv_bfloat16* __restrict__ kl,
                 const __nv_bfloat16* __restrict__ vh, const __nv_bfloat16* __restrict__ vl,
                 float* __restrict__ ao)
{
    extern __shared__ char smem[];
    const uint32_t sb = smem_u32(smem);

    const int tid  = threadIdx.x;
    const int lane = tid & 31;
    const int w    = tid >> 5;
    const int qi   = gridDim.x - 1 - blockIdx.x;
    const int h    = blockIdx.y;
    const int b    = blockIdx.z;
    const int kvh  = h >> 1;

#pragma unroll
    for (int i = 0; i < 8; i++) {
        const int idx = tid + i * 256;
        const int row = idx >> 4, ch = idx & 15;
        const size_t g = ((size_t)(b * S_) + qi * 128 + row) * (NH_ * D_) + h * D_ + ch * 8;
        cp16(sb + row * 272 + ch * 16,            qh + g);
        cp16(sb + AQ_BYTES + row * 272 + ch * 16, ql + g);
    }
    {
        const uint32_t buf = sb + ABUF0;
#pragma unroll
        for (int i = 0; i < 4; i++) {
            const int idx = tid + i * 256;
            const int row = idx >> 4, ch = idx & 15;
            const size_t g = ((size_t)(b * S_) + row) * (NKV_ * D_) + kvh * D_ + ch * 8;
            const uint32_t so = buf + row * 272 + ch * 16;
            cp16(so,                 kh + g);
            cp16(so + AKV_BYTES,     kl + g);
            cp16(so + 2 * AKV_BYTES, vh + g);
            cp16(so + 3 * AKV_BYTES, vl + g);
        }
    }
    cp_commit();

    float oacc[16][4];
#pragma unroll
    for (int i = 0; i < 16; i++)
#pragma unroll
        for (int e = 0; e < 4; e++) oacc[i][e] = 0.f;
    float m_i[2] = {-1e30f, -1e30f};
    float l_i[2] = {0.f, 0.f};

    const uint32_t lrow16 = (uint32_t)(lane & 15);
    const uint32_t lhalf  = (uint32_t)(lane >> 4) * 16;
    const int jmax = 2 * qi + 1;

    for (int jb = 0; jb <= jmax; jb++) {
        if (jb < jmax) {
            const uint32_t buf = sb + ABUF0 + ((jb + 1) & 1) * ABUFSZ;
#pragma unroll
            for (int i = 0; i < 4; i++) {
                const int idx = tid + i * 256;
                const int row = idx >> 4, ch = idx & 15;
                const size_t g = ((size_t)(b * S_) + (jb + 1) * 64 + row) * (NKV_ * D_) +
                                 kvh * D_ + ch * 8;
                const uint32_t so = buf + row * 272 + ch * 16;
                cp16(so,                 kh + g);
                cp16(so + AKV_BYTES,     kl + g);
                cp16(so + 2 * AKV_BYTES, vh + g);
                cp16(so + 3 * AKV_BYTES, vl + g);
            }
            cp_commit();
            cp_wait1();
        } else {
            cp_wait0();
        }
        __syncthreads();

        const uint32_t kb = sb + ABUF0 + (jb & 1) * ABUFSZ;
        const bool skip = (jb * 64) > (qi * 128 + w * 16 + 15);

        if (!skip) {
            float sacc[8][4];
#pragma unroll
            for (int i = 0; i < 8; i++)
#pragma unroll
                for (int e = 0; e < 4; e++) sacc[i][e] = 0.f;

            const uint32_t qbase = sb + ((uint32_t)(w * 16) + lrow16) * 272 + lhalf;
#pragma unroll
            for (int ks = 0; ks < 8; ks++) {
                uint32_t ahi[4], alo[4];
                ldsm_x4(ahi, qbase + ks * 32);
                ldsm_x4(alo, qbase + AQ_BYTES + ks * 32);
#pragma unroll
                for (int ng = 0; ng < 4; ng++) {
                    uint32_t t[4], u[4];
                    const uint32_t ka = kb + ((uint32_t)(ng * 16) + lrow16) * 272 + ks * 32 + lhalf;
                    ldsm_x4(t, ka);
                    ldsm_x4(u, ka + AKV_BYTES);
                    uint32_t bh0[2] = {t[0], t[2]}, bh1[2] = {t[1], t[3]};
                    uint32_t bl0[2] = {u[0], u[2]}, bl1[2] = {u[1], u[3]};
                    mma_bf16(sacc[ng * 2],     ahi, bh0);
                    mma_bf16(sacc[ng * 2 + 1], ahi, bh1);
                    mma_bf16(sacc[ng * 2],     ahi, bl0);
                    mma_bf16(sacc[ng * 2 + 1], ahi, bl1);
                    mma_bf16(sacc[ng * 2],     alo, bh0);
                    mma_bf16(sacc[ng * 2 + 1], alo, bh1);
                }
            }

            const float sc = 0.088388347648318447f;
            const bool domask = (jb * 64 + 63) > (qi * 128 + w * 16);
#pragma unroll
            for (int nf = 0; nf < 8; nf++)
#pragma unroll
                for (int e = 0; e < 4; e++) {
                    float s = sacc[nf][e] * sc;
                    if (domask) {
                        const int col = jb * 64 + nf * 8 + ((lane & 3) << 1) + (e & 1);
                        const int row = qi * 128 + w * 16 + (lane >> 2) + ((e >> 1) << 3);
                        if (col > row) s = -1e30f;
                    }
                    sacc[nf][e] = s;
                }

#pragma unroll
            for (int r2 = 0; r2 < 2; r2++) {
                float mx = -1e30f;
#pragma unroll
                for (int nf = 0; nf < 8; nf++)
                    mx = fmaxf(mx, fmaxf(sacc[nf][2 * r2], sacc[nf][2 * r2 + 1]));
                mx = fmaxf(mx, __shfl_xor_sync(0xffffffffu, mx, 1));
                mx = fmaxf(mx, __shfl_xor_sync(0xffffffffu, mx, 2));
                const float mn = fmaxf(m_i[r2], mx);
                const float alpha = __expf(m_i[r2] - mn);
                m_i[r2] = mn;
                float rs = 0.f;
#pragma unroll
                for (int nf = 0; nf < 8; nf++) {
                    float p0 = __expf(sacc[nf][2 * r2]     - mn);
                    float p1 = __expf(sacc[nf][2 * r2 + 1] - mn);
                    sacc[nf][2 * r2]     = p0;
                    sacc[nf][2 * r2 + 1] = p1;
                    rs += p0 + p1;
                }
                rs += __shfl_xor_sync(0xffffffffu, rs, 1);
                rs += __shfl_xor_sync(0xffffffffu, rs, 2);
                l_i[r2] = l_i[r2] * alpha + rs;
#pragma unroll
                for (int ndf = 0; ndf < 16; ndf++) {
                    oacc[ndf][2 * r2]     *= alpha;
                    oacc[ndf][2 * r2 + 1] *= alpha;
                }
            }

#pragma unroll
            for (int kk = 0; kk < 4; kk++) {
                uint32_t phi[4], plo[4];
                split_pair(sacc[2 * kk][0],     sacc[2 * kk][1],     phi[0], plo[0]);
                split_pair(sacc[2 * kk][2],     sacc[2 * kk][3],     phi[1], plo[1]);
                split_pair(sacc[2 * kk + 1][0], sacc[2 * kk + 1][1], phi[2], plo[2]);
                split_pair(sacc[2 * kk + 1][2], sacc[2 * kk + 1][3], phi[3], plo[3]);
#pragma unroll
                for (int ndg = 0; ndg < 8; ndg++) {
                    uint32_t t[4], u[4];
                    const uint32_t va = kb + 2 * AKV_BYTES +
                        ((uint32_t)(kk * 16) + lrow16) * 272 + ndg * 32 + lhalf;
                    ldsm_x4_trans(t, va);
                    ldsm_x4_trans(u, va + AKV_BYTES);
                    uint32_t bh0[2] = {t[0], t[1]}, bh1[2] = {t[2], t[3]};
                    uint32_t bl0[2] = {u[0], u[1]}, bl1[2] = {u[2], u[3]};
                    mma_bf16(oacc[ndg * 2],     phi, bh0);
                    mma_bf16(oacc[ndg * 2 + 1], phi, bh1);
                    mma_bf16(oacc[ndg * 2],     phi, bl0);
                    mma_bf16(oacc[ndg * 2 + 1], phi, bl1);
                    mma_bf16(oacc[ndg * 2],     plo, bh0);
                    mma_bf16(oacc[ndg * 2 + 1], plo, bh1);
                }
            }
        }
        __syncthreads();
    }

    const float i0 = 1.0f / l_i[0];
    const float i1 = 1.0f / l_i[1];
    const int row0 = qi * 128 + w * 16 + (lane >> 2);
    const size_t base0 = ((size_t)(b * S_) + row0) * (NH_ * D_) + h * D_ + (lane & 3) * 2;
    const size_t base1 = base0 + (size_t)8 * (NH_ * D_);
#pragma unroll
    for (int ndf = 0; ndf < 16; ndf++) {
        *reinterpret_cast<float2*>(ao + base0 + ndf * 8) =
            make_float2(oacc[ndf][0] * i0, oacc[ndf][1] * i0);
        *reinterpret_cast<float2*>(ao + base1 + ndf * 8) =
            make_float2(oacc[ndf][2] * i1, oacc[ndf][3] * i1);
    }
}

// ---------------------------------------------------------------------------
// Launch
// ---------------------------------------------------------------------------
extern "C" void kernel_launch(void* const* d_in, const int* in_sizes, int n_in,
                              void* d_out, int out_size)
{
    const float* hidden = (const float*)d_in[0];
    const float* cosb   = (const float*)d_in[1];
    const float* sinb   = (const float*)d_in[2];
    const float* Wq     = (const float*)d_in[3];
    const float* Wk     = (const float*)d_in[4];
    const float* Wv     = (const float*)d_in[5];
    const float* Wo     = (const float*)d_in[6];
    const float* qw     = (const float*)d_in[7];
    const float* kw     = (const float*)d_in[8];
    float* out = (float*)d_out;

    float *gq, *gk, *gv, *gao;
    cudaGetSymbolAddress((void**)&gq,  g_q);
    cudaGetSymbolAddress((void**)&gk,  g_k);
    cudaGetSymbolAddress((void**)&gv,  g_v);
    cudaGetSymbolAddress((void**)&gao, g_ao);
    __nv_bfloat16 *qh, *ql, *kh, *kl, *vh, *vl;
    cudaGetSymbolAddress((void**)&qh, g_qh);
    cudaGetSymbolAddress((void**)&ql, g_ql);
    cudaGetSymbolAddress((void**)&kh, g_kh);
    cudaGetSymbolAddress((void**)&kl, g_kl);
    cudaGetSymbolAddress((void**)&vh, g_vh);
    cudaGetSymbolAddress((void**)&vl, g_vl);

    cudaFuncSetAttribute((const void*)gemm_qkv,
                         cudaFuncAttributeMaxDynamicSharedMemorySize, GSMEM);
    cudaFuncSetAttribute((const void*)gemm_nt,
                         cudaFuncAttributeMaxDynamicSharedMemorySize, GSMEM);
    cudaFuncSetAttribute((const void*)attn_bf16_kernel,
                         cudaFuncAttributeMaxDynamicSharedMemorySize, ATTN_SMEM);

    // merged QKV projection (1024 CTAs, staggered-pipeline bf16x3 tensor GEMM)
    gemm_qkv<<<dim3(32, TOK / 128), 512, GSMEM>>>(hidden, Wq, Wk, Wv, gq, gk, gv);

    // fused RMSNorm + RoPE + split (warp per row)
    rms_rope_split2<<<TOK * 32 / 8, 256>>>(gq, gk, gv, cosb, sinb, qw, kw,
                                           qh, ql, kh, kl, vh, vl);

    // tensor-core causal flash attention
    attn_bf16_kernel<<<dim3(S_ / 128, NH_, B_), 256, ATTN_SMEM>>>(
        qh, ql, kh, kl, vh, vl, gao);

    // output projection
    gemm_nt<<<dim3(H_ / 128, TOK / 128), 512, GSMEM>>>(
        gao, Wo, out, TOK, H_, NH_ * D_);
}